// round 4
// baseline (speedup 1.0000x reference)
#include <cuda_runtime.h>
#include <math.h>

#define BATCH 256
#define NA    32
#define OBS   128
#define ACT   8
#define DV    128
#define DH    64
#define DO    8
#define S1    132   // padded stride (floats) for 128-wide rows, 16B-aligned rows
#define S2    68    // padded stride for 64-wide rows

// ---- SMEM layout (floats) ----
#define OFF_STATES 0
#define OFF_T      (OFF_STATES + NA*S1)
#define OFF_AVA    (OFF_T + NA*S1)
#define OFF_DIFF   (OFF_AVA + NA*S1)
#define OFF_W      (OFF_DIFF + NA*S1)
#define OFF_AW1    (OFF_W + NA*NA)
#define OFF_DW1    (OFF_AW1 + NA*S2)
#define OFF_BW1    (OFF_DW1 + NA*S2)
#define OFF_ACT    (OFF_BW1 + NA*S2)
#define OFF_POL    (OFF_ACT + NA*ACT)
#define OFF_W2     (OFF_POL + NA*ACT)
#define SMEM_FLOATS (OFF_W2 + DH*DO)
#define SMEM_BYTES  (SMEM_FLOATS * 4)

typedef unsigned long long u64;

__device__ __forceinline__ u64 pack2(float x) {
    u64 r; asm("mov.b64 %0, {%1, %1};" : "=l"(r) : "f"(x)); return r;
}
__device__ __forceinline__ u64 ffma2(u64 a, u64 b, u64 c) {
    u64 d; asm("fma.rn.f32x2 %0, %1, %2, %3;" : "=l"(d) : "l"(a), "l"(b), "l"(c)); return d;
}
__device__ __forceinline__ float2 unpack2(u64 v) {
    float2 f; asm("mov.b64 {%0, %1}, %2;" : "=f"(f.x), "=f"(f.y) : "l"(v)); return f;
}

__device__ float g_M[OBS * OBS];   // (Wq @ Wk^T) * (1/sqrt(DK)), contract over DK

// ---------------------------------------------------------------------------
// M[i][j] = (sum_d Wq[i][d] * Wk[j][d]) / sqrt(128)
// ---------------------------------------------------------------------------
__global__ void compute_M_kernel(const float* __restrict__ Wq,
                                 const float* __restrict__ Wk) {
    __shared__ float qs[16][OBS + 4];
    __shared__ float ks[16][OBS + 4];
    const int i0 = (blockIdx.x & 7) * 16;
    const int j0 = (blockIdx.x >> 3) * 16;
    const int tid = threadIdx.x;
    for (int idx = tid; idx < 16 * 32; idx += 256) {
        int r = idx >> 5, d4 = (idx & 31) * 4;
        *reinterpret_cast<float4*>(&qs[r][d4]) =
            *reinterpret_cast<const float4*>(&Wq[(i0 + r) * OBS + d4]);
        *reinterpret_cast<float4*>(&ks[r][d4]) =
            *reinterpret_cast<const float4*>(&Wk[(j0 + r) * OBS + d4]);
    }
    __syncthreads();
    const int ti = tid >> 4, tj = tid & 15;
    float acc = 0.f;
    #pragma unroll 8
    for (int d = 0; d < OBS; ++d)
        acc = fmaf(qs[ti][d], ks[tj][d], acc);
    g_M[(i0 + ti) * OBS + j0 + tj] = acc * 0.08838834764831845f;
}

// ---------------------------------------------------------------------------
// Main fused kernel: one CTA per batch element, 256 threads
// ---------------------------------------------------------------------------
__global__ __launch_bounds__(256, 2)
void critic_kernel(const float* __restrict__ states,
                   const float* __restrict__ policies,
                   const float* __restrict__ actions,
                   const float* __restrict__ Wv,
                   const float* __restrict__ W1,
                   const float* __restrict__ W2,
                   float* __restrict__ value_out,
                   float* __restrict__ weight_out)
{
    extern __shared__ float sm[];
    float* s_states = sm + OFF_STATES;
    float* s_t      = sm + OFF_T;
    float* s_avA    = sm + OFF_AVA;
    float* s_diff   = sm + OFF_DIFF;
    float* s_w      = sm + OFF_W;
    float* s_aW1    = sm + OFF_AW1;
    float* s_dW1    = sm + OFF_DW1;
    float* s_bW1    = sm + OFF_BW1;
    float* s_act    = sm + OFF_ACT;
    float* s_pol    = sm + OFF_POL;
    float* s_W2     = sm + OFF_W2;

    const int b   = blockIdx.x;
    const int tid = threadIdx.x;

    // ---- stage inputs ----
    {
        const float* st_b = states + (size_t)b * NA * OBS;
        for (int idx = tid; idx < NA * OBS / 4; idx += 256) {
            int i = idx >> 5, d4 = (idx & 31) * 4;
            *reinterpret_cast<float4*>(&s_states[i * S1 + d4]) =
                *reinterpret_cast<const float4*>(&st_b[i * OBS + d4]);
        }
        for (int idx = tid; idx < NA * ACT; idx += 256) {
            s_act[idx] = actions [(size_t)b * NA * ACT + idx];
            s_pol[idx] = policies[(size_t)b * NA * ACT + idx];
        }
        for (int idx = tid; idx < DH * DO; idx += 256) s_W2[idx] = W2[idx];
    }
    __syncthreads();

    // =========================================================================
    // Phase 1: t = states@M  and  avA/diff = tanh(concat@Wv), FFMA2 packed.
    // Thread tile: 4 rows x 4 cols (as 2x f32x2 lanes).
    // =========================================================================
    {
        const int r0 = (tid >> 5) * 4;
        const int c0 = (tid & 31) * 4;
        u64 tAcc[4][2], vAcc[4][2];
        #pragma unroll
        for (int r = 0; r < 4; ++r) {
            tAcc[r][0] = 0ull; tAcc[r][1] = 0ull;
            vAcc[r][0] = 0ull; vAcc[r][1] = 0ull;
        }
        for (int kk = 0; kk < OBS; kk += 4) {
            float4 sv[4];
            #pragma unroll
            for (int r = 0; r < 4; ++r)
                sv[r] = *reinterpret_cast<const float4*>(&s_states[(r0 + r) * S1 + kk]);
            #pragma unroll
            for (int t = 0; t < 4; ++t) {
                ulonglong2 mq = *reinterpret_cast<const ulonglong2*>(&g_M[(kk + t) * OBS + c0]);
                ulonglong2 wv = *reinterpret_cast<const ulonglong2*>(&Wv [(kk + t) * DV  + c0]);
                #pragma unroll
                for (int r = 0; r < 4; ++r) {
                    u64 ss = pack2(reinterpret_cast<const float*>(&sv[r])[t]);
                    tAcc[r][0] = ffma2(ss, mq.x, tAcc[r][0]);
                    tAcc[r][1] = ffma2(ss, mq.y, tAcc[r][1]);
                    vAcc[r][0] = ffma2(ss, wv.x, vAcc[r][0]);
                    vAcc[r][1] = ffma2(ss, wv.y, vAcc[r][1]);
                }
            }
        }
        #pragma unroll
        for (int r = 0; r < 4; ++r)
            *reinterpret_cast<ulonglong2*>(&s_t[(r0 + r) * S1 + c0]) =
                make_ulonglong2(tAcc[r][0], tAcc[r][1]);

        // action/policy tail on the shared states partial
        u64 aAcc[4][2], pAcc[4][2];
        #pragma unroll
        for (int r = 0; r < 4; ++r) {
            aAcc[r][0] = vAcc[r][0]; aAcc[r][1] = vAcc[r][1];
            pAcc[r][0] = vAcc[r][0]; pAcc[r][1] = vAcc[r][1];
        }
        #pragma unroll
        for (int kk = 0; kk < ACT; ++kk) {
            ulonglong2 wv = *reinterpret_cast<const ulonglong2*>(&Wv[(OBS + kk) * DV + c0]);
            #pragma unroll
            for (int r = 0; r < 4; ++r) {
                u64 pa = pack2(s_act[(r0 + r) * ACT + kk]);
                u64 pp = pack2(s_pol[(r0 + r) * ACT + kk]);
                aAcc[r][0] = ffma2(pa, wv.x, aAcc[r][0]);
                aAcc[r][1] = ffma2(pa, wv.y, aAcc[r][1]);
                pAcc[r][0] = ffma2(pp, wv.x, pAcc[r][0]);
                pAcc[r][1] = ffma2(pp, wv.y, pAcc[r][1]);
            }
        }
        #pragma unroll
        for (int r = 0; r < 4; ++r) {
            float2 a0 = unpack2(aAcc[r][0]), a1 = unpack2(aAcc[r][1]);
            float2 p0 = unpack2(pAcc[r][0]), p1 = unpack2(pAcc[r][1]);
            float4 tA, dF;
            tA.x = tanhf(a0.x); tA.y = tanhf(a0.y);
            tA.z = tanhf(a1.x); tA.w = tanhf(a1.y);
            dF.x = tanhf(p0.x) - tA.x; dF.y = tanhf(p0.y) - tA.y;
            dF.z = tanhf(p1.x) - tA.z; dF.w = tanhf(p1.y) - tA.w;
            *reinterpret_cast<float4*>(&s_avA [(r0 + r) * S1 + c0]) = tA;
            *reinterpret_cast<float4*>(&s_diff[(r0 + r) * S1 + c0]) = dF;
        }
    }
    __syncthreads();

    // =========================================================================
    // Phase 2a: score[i][j] = t[i,:] . states[j,:]   (scale already in M)
    // Rows 4w..4w+3 are produced entirely within warp w.
    // =========================================================================
    {
        const int i0 = (tid >> 4) * 2;
        const int j0 = (tid & 15) * 2;
        u64 a00 = 0ull, a01 = 0ull, a10 = 0ull, a11 = 0ull;
        for (int kk = 0; kk < OBS; kk += 4) {
            ulonglong2 q0 = *reinterpret_cast<const ulonglong2*>(&s_t[ i0      * S1 + kk]);
            ulonglong2 q1 = *reinterpret_cast<const ulonglong2*>(&s_t[(i0 + 1) * S1 + kk]);
            ulonglong2 k0 = *reinterpret_cast<const ulonglong2*>(&s_states[ j0      * S1 + kk]);
            ulonglong2 k1 = *reinterpret_cast<const ulonglong2*>(&s_states[(j0 + 1) * S1 + kk]);
            a00 = ffma2(q0.x, k0.x, a00); a00 = ffma2(q0.y, k0.y, a00);
            a01 = ffma2(q0.x, k1.x, a01); a01 = ffma2(q0.y, k1.y, a01);
            a10 = ffma2(q1.x, k0.x, a10); a10 = ffma2(q1.y, k0.y, a10);
            a11 = ffma2(q1.x, k1.x, a11); a11 = ffma2(q1.y, k1.y, a11);
        }
        float2 v00 = unpack2(a00), v01 = unpack2(a01);
        float2 v10 = unpack2(a10), v11 = unpack2(a11);
        s_w[i0 * NA + j0]           = v00.x + v00.y;
        s_w[i0 * NA + j0 + 1]       = v01.x + v01.y;
        s_w[(i0 + 1) * NA + j0]     = v10.x + v10.y;
        s_w[(i0 + 1) * NA + j0 + 1] = v11.x + v11.y;
    }
    __syncwarp();

    // =========================================================================
    // Phase 2a': softmax — warp w owns rows 4w..4w+3 (only warp sync needed)
    // =========================================================================
    {
        const int warp = tid >> 5, lane = tid & 31;
        #pragma unroll
        for (int rr = 0; rr < 4; ++rr) {
            const int row = warp * 4 + rr;
            float v = s_w[row * NA + lane];
            float m = v;
            #pragma unroll
            for (int off = 16; off > 0; off >>= 1)
                m = fmaxf(m, __shfl_xor_sync(0xffffffffu, m, off));
            float e = expf(v - m);
            float s = e;
            #pragma unroll
            for (int off = 16; off > 0; off >>= 1)
                s += __shfl_xor_sync(0xffffffffu, s, off);
            float w = e / s;
            s_w[row * NA + lane] = w;
            weight_out[(size_t)b * NA * NA + row * NA + lane] = w;
        }
    }

    // =========================================================================
    // Phase 2b: aW1 = avA@W1, dW1 = diff@W1. 1 row x 8 h per thread, FFMA2.
    // =========================================================================
    {
        const int j  = tid >> 3;          // 0..31
        const int h0 = (tid & 7) * 8;     // 0..56
        u64 accA[4] = {0ull, 0ull, 0ull, 0ull};
        u64 accD[4] = {0ull, 0ull, 0ull, 0ull};
        for (int d = 0; d < DV; d += 4) {
            float4 av = *reinterpret_cast<const float4*>(&s_avA [j * S1 + d]);
            float4 df = *reinterpret_cast<const float4*>(&s_diff[j * S1 + d]);
            #pragma unroll
            for (int t = 0; t < 4; ++t) {
                ulonglong2 w1a = *reinterpret_cast<const ulonglong2*>(&W1[(d + t) * DH + h0]);
                ulonglong2 w1b = *reinterpret_cast<const ulonglong2*>(&W1[(d + t) * DH + h0 + 4]);
                u64 pa = pack2(reinterpret_cast<const float*>(&av)[t]);
                u64 pd = pack2(reinterpret_cast<const float*>(&df)[t]);
                accA[0] = ffma2(pa, w1a.x, accA[0]); accA[1] = ffma2(pa, w1a.y, accA[1]);
                accA[2] = ffma2(pa, w1b.x, accA[2]); accA[3] = ffma2(pa, w1b.y, accA[3]);
                accD[0] = ffma2(pd, w1a.x, accD[0]); accD[1] = ffma2(pd, w1a.y, accD[1]);
                accD[2] = ffma2(pd, w1b.x, accD[2]); accD[3] = ffma2(pd, w1b.y, accD[3]);
            }
        }
        *reinterpret_cast<ulonglong2*>(&s_aW1[j * S2 + h0])     = make_ulonglong2(accA[0], accA[1]);
        *reinterpret_cast<ulonglong2*>(&s_aW1[j * S2 + h0 + 4]) = make_ulonglong2(accA[2], accA[3]);
        *reinterpret_cast<ulonglong2*>(&s_dW1[j * S2 + h0])     = make_ulonglong2(accD[0], accD[1]);
        *reinterpret_cast<ulonglong2*>(&s_dW1[j * S2 + h0 + 4]) = make_ulonglong2(accD[2], accD[3]);
    }
    __syncthreads();

    // =========================================================================
    // Phase 4: bW1 = w @ aW1. 1 a-row x 8 h per thread, FFMA2.
    // =========================================================================
    {
        const int a  = tid >> 3;
        const int h0 = (tid & 7) * 8;
        u64 acc[4] = {0ull, 0ull, 0ull, 0ull};
        #pragma unroll
        for (int j = 0; j < NA; j += 4) {
            float4 wq = *reinterpret_cast<const float4*>(&s_w[a * NA + j]);
            #pragma unroll
            for (int t = 0; t < 4; ++t) {
                ulonglong2 x = *reinterpret_cast<const ulonglong2*>(&s_aW1[(j + t) * S2 + h0]);
                ulonglong2 y = *reinterpret_cast<const ulonglong2*>(&s_aW1[(j + t) * S2 + h0 + 4]);
                u64 pw = pack2(reinterpret_cast<const float*>(&wq)[t]);
                acc[0] = ffma2(pw, x.x, acc[0]); acc[1] = ffma2(pw, x.y, acc[1]);
                acc[2] = ffma2(pw, y.x, acc[2]); acc[3] = ffma2(pw, y.y, acc[3]);
            }
        }
        *reinterpret_cast<ulonglong2*>(&s_bW1[a * S2 + h0])     = make_ulonglong2(acc[0], acc[1]);
        *reinterpret_cast<ulonglong2*>(&s_bW1[a * S2 + h0 + 4]) = make_ulonglong2(acc[2], acc[3]);
    }
    __syncthreads();

    // =========================================================================
    // Phase 5: per (a,c): h = leaky(bW1[a] + w*dW1[c]); out = h @ W2.
    // 4 a-values per thread; FFMA2 on the 8-wide W2 accumulation.
    // =========================================================================
    {
        const int a0 = tid >> 5;      // 0..7
        const int c  = tid & 31;      // 0..31
        float wk[4];
        #pragma unroll
        for (int k = 0; k < 4; ++k) wk[k] = s_w[(a0 + 8 * k) * NA + c];

        u64 acc[4][4];
        #pragma unroll
        for (int k = 0; k < 4; ++k)
            #pragma unroll
            for (int q = 0; q < 4; ++q) acc[k][q] = 0ull;

        for (int h = 0; h < DH; h += 4) {
            float4 dq = *reinterpret_cast<const float4*>(&s_dW1[c * S2 + h]);
            ulonglong2 w2a[4], w2b[4];
            #pragma unroll
            for (int t = 0; t < 4; ++t) {
                w2a[t] = *reinterpret_cast<const ulonglong2*>(&s_W2[(h + t) * DO]);
                w2b[t] = *reinterpret_cast<const ulonglong2*>(&s_W2[(h + t) * DO + 4]);
            }
            #pragma unroll
            for (int k = 0; k < 4; ++k) {
                float4 bq = *reinterpret_cast<const float4*>(&s_bW1[(a0 + 8 * k) * S2 + h]);
                #pragma unroll
                for (int t = 0; t < 4; ++t) {
                    float x = fmaf(wk[k],
                                   reinterpret_cast<const float*>(&dq)[t],
                                   reinterpret_cast<const float*>(&bq)[t]);
                    x = fmaxf(x, 0.01f * x);   // leaky_relu(0.01)
                    u64 px = pack2(x);
                    acc[k][0] = ffma2(px, w2a[t].x, acc[k][0]);
                    acc[k][1] = ffma2(px, w2a[t].y, acc[k][1]);
                    acc[k][2] = ffma2(px, w2b[t].x, acc[k][2]);
                    acc[k][3] = ffma2(px, w2b[t].y, acc[k][3]);
                }
            }
        }
        #pragma unroll
        for (int k = 0; k < 4; ++k) {
            ulonglong2* outp = reinterpret_cast<ulonglong2*>(
                value_out + (((size_t)b * NA + (a0 + 8 * k)) * NA + c) * DO);
            outp[0] = make_ulonglong2(acc[k][0], acc[k][1]);
            outp[1] = make_ulonglong2(acc[k][2], acc[k][3]);
        }
    }
}

extern "C" void kernel_launch(void* const* d_in, const int* in_sizes, int n_in,
                              void* d_out, int out_size) {
    const float* states   = (const float*)d_in[0];
    const float* policies = (const float*)d_in[1];
    const float* actions  = (const float*)d_in[2];
    const float* Wk       = (const float*)d_in[3];
    const float* Wq       = (const float*)d_in[4];
    const float* Wv       = (const float*)d_in[5];
    const float* W1       = (const float*)d_in[6];
    const float* W2       = (const float*)d_in[7];

    float* value_out  = (float*)d_out;                              // [B,N,N,8]
    float* weight_out = value_out + (size_t)BATCH * NA * NA * DO;   // [B,N,N]

    compute_M_kernel<<<64, 256>>>(Wq, Wk);

    cudaFuncSetAttribute(critic_kernel,
                         cudaFuncAttributeMaxDynamicSharedMemorySize, SMEM_BYTES);
    critic_kernel<<<BATCH, 256, SMEM_BYTES>>>(
        states, policies, actions, Wv, W1, W2, value_out, weight_out);
}

// round 5
// speedup vs baseline: 1.1669x; 1.1669x over previous
#include <cuda_runtime.h>
#include <math.h>

#define BATCH 256
#define NA    32
#define OBS   128
#define ACT   8
#define DV    128
#define DH    64
#define DO    8
#define S1    132   // padded stride (floats) for 128-wide rows, float4-aligned
#define S2    68    // padded stride for 64-wide rows

// ---- SMEM layout (floats) ----
#define OFF_STATES 0
#define OFF_T      (OFF_STATES + NA*S1)
#define OFF_AVA    (OFF_T + NA*S1)
#define OFF_DIFF   (OFF_AVA + NA*S1)
#define OFF_W      (OFF_DIFF + NA*S1)
#define OFF_AW1    (OFF_W + NA*NA)
#define OFF_DW1    (OFF_AW1 + NA*S2)
#define OFF_BW1    (OFF_DW1 + NA*S2)
#define OFF_ACT    (OFF_BW1 + NA*S2)
#define OFF_POL    (OFF_ACT + NA*ACT)
#define OFF_W2     (OFF_POL + NA*ACT)
#define SMEM_FLOATS (OFF_W2 + DH*DO)
#define SMEM_BYTES  (SMEM_FLOATS * 4)

__device__ float g_M[OBS * OBS];   // (Wq @ Wk^T) / sqrt(DK), contract over DK

// ---------------------------------------------------------------------------
// M[i][j] = (sum_d Wq[i][d] * Wk[j][d]) / sqrt(128)
// ---------------------------------------------------------------------------
__global__ void compute_M_kernel(const float* __restrict__ Wq,
                                 const float* __restrict__ Wk) {
    __shared__ float qs[16][OBS + 4];
    __shared__ float ks[16][OBS + 4];
    const int i0 = (blockIdx.x & 7) * 16;
    const int j0 = (blockIdx.x >> 3) * 16;
    const int tid = threadIdx.x;
    for (int idx = tid; idx < 16 * 32; idx += 256) {
        int r = idx >> 5, d4 = (idx & 31) * 4;
        *reinterpret_cast<float4*>(&qs[r][d4]) =
            *reinterpret_cast<const float4*>(&Wq[(i0 + r) * OBS + d4]);
        *reinterpret_cast<float4*>(&ks[r][d4]) =
            *reinterpret_cast<const float4*>(&Wk[(j0 + r) * OBS + d4]);
    }
    __syncthreads();
    const int ti = tid >> 4, tj = tid & 15;
    float acc = 0.f;
    #pragma unroll 8
    for (int d = 0; d < OBS; ++d)
        acc = fmaf(qs[ti][d], ks[tj][d], acc);
    g_M[(i0 + ti) * OBS + j0 + tj] = acc * 0.08838834764831845f;
}

// ---------------------------------------------------------------------------
// Main fused kernel: one CTA per batch element, 256 threads
// ---------------------------------------------------------------------------
__global__ __launch_bounds__(256, 2)
void critic_kernel(const float* __restrict__ states,
                   const float* __restrict__ policies,
                   const float* __restrict__ actions,
                   const float* __restrict__ Wv,
                   const float* __restrict__ W1,
                   const float* __restrict__ W2,
                   float* __restrict__ value_out,
                   float* __restrict__ weight_out)
{
    extern __shared__ float sm[];
    float* s_states = sm + OFF_STATES;
    float* s_t      = sm + OFF_T;
    float* s_avA    = sm + OFF_AVA;
    float* s_diff   = sm + OFF_DIFF;
    float* s_w      = sm + OFF_W;
    float* s_aW1    = sm + OFF_AW1;
    float* s_dW1    = sm + OFF_DW1;
    float* s_bW1    = sm + OFF_BW1;
    float* s_act    = sm + OFF_ACT;
    float* s_pol    = sm + OFF_POL;
    float* s_W2     = sm + OFF_W2;

    const int b   = blockIdx.x;
    const int tid = threadIdx.x;

    // ---- stage inputs ----
    {
        const float* st_b = states + (size_t)b * NA * OBS;
        for (int idx = tid; idx < NA * OBS / 4; idx += 256) {
            int i = idx >> 5, d4 = (idx & 31) * 4;
            *reinterpret_cast<float4*>(&s_states[i * S1 + d4]) =
                *reinterpret_cast<const float4*>(&st_b[i * OBS + d4]);
        }
        for (int idx = tid; idx < NA * ACT; idx += 256) {
            s_act[idx] = actions [(size_t)b * NA * ACT + idx];
            s_pol[idx] = policies[(size_t)b * NA * ACT + idx];
        }
        for (int idx = tid; idx < DH * DO; idx += 256) s_W2[idx] = W2[idx];
    }
    __syncthreads();

    // =========================================================================
    // Phase 1: t = states@M and avA/diff = tanh(concat@Wv).
    // Warp w owns cols [16w,16w+16) for ALL 32 rows -> unique M/Wv traffic
    // per warp is 8KB each (8x less L1 traffic than row-major warp mapping).
    // Lane: c0 = 16w + (l&3)*4 ; rows {g, g+8, g+16, g+24}, g = l>>2
    // (rows within one load instruction are == g mod 8 -> distinct bank groups)
    // =========================================================================
    {
        const int w  = tid >> 5;
        const int l  = tid & 31;
        const int g  = l >> 2;
        const int c0 = w * 16 + (l & 3) * 4;

        float4 tAcc[4], vAcc[4];
        #pragma unroll
        for (int m = 0; m < 4; ++m) {
            tAcc[m] = make_float4(0.f, 0.f, 0.f, 0.f);
            vAcc[m] = make_float4(0.f, 0.f, 0.f, 0.f);
        }
        for (int kk = 0; kk < OBS; kk += 4) {
            float4 sv[4];
            #pragma unroll
            for (int m = 0; m < 4; ++m)
                sv[m] = *reinterpret_cast<const float4*>(&s_states[(g + 8 * m) * S1 + kk]);
            #pragma unroll
            for (int t = 0; t < 4; ++t) {
                float4 mq = *reinterpret_cast<const float4*>(&g_M[(kk + t) * OBS + c0]);
                float4 wv = *reinterpret_cast<const float4*>(&Wv [(kk + t) * DV  + c0]);
                #pragma unroll
                for (int m = 0; m < 4; ++m) {
                    float s = reinterpret_cast<const float*>(&sv[m])[t];
                    tAcc[m].x = fmaf(s, mq.x, tAcc[m].x);
                    tAcc[m].y = fmaf(s, mq.y, tAcc[m].y);
                    tAcc[m].z = fmaf(s, mq.z, tAcc[m].z);
                    tAcc[m].w = fmaf(s, mq.w, tAcc[m].w);
                    vAcc[m].x = fmaf(s, wv.x, vAcc[m].x);
                    vAcc[m].y = fmaf(s, wv.y, vAcc[m].y);
                    vAcc[m].z = fmaf(s, wv.z, vAcc[m].z);
                    vAcc[m].w = fmaf(s, wv.w, vAcc[m].w);
                }
            }
        }
        #pragma unroll
        for (int m = 0; m < 4; ++m)
            *reinterpret_cast<float4*>(&s_t[(g + 8 * m) * S1 + c0]) = tAcc[m];

        // action/policy tail (8 extra K) on the shared states partial
        float4 accA[4], accP[4];
        #pragma unroll
        for (int m = 0; m < 4; ++m) { accA[m] = vAcc[m]; accP[m] = vAcc[m]; }
        #pragma unroll
        for (int kk = 0; kk < ACT; ++kk) {
            float4 wv = *reinterpret_cast<const float4*>(&Wv[(OBS + kk) * DV + c0]);
            #pragma unroll
            for (int m = 0; m < 4; ++m) {
                float a = s_act[(g + 8 * m) * ACT + kk];
                float p = s_pol[(g + 8 * m) * ACT + kk];
                accA[m].x = fmaf(a, wv.x, accA[m].x);
                accA[m].y = fmaf(a, wv.y, accA[m].y);
                accA[m].z = fmaf(a, wv.z, accA[m].z);
                accA[m].w = fmaf(a, wv.w, accA[m].w);
                accP[m].x = fmaf(p, wv.x, accP[m].x);
                accP[m].y = fmaf(p, wv.y, accP[m].y);
                accP[m].z = fmaf(p, wv.z, accP[m].z);
                accP[m].w = fmaf(p, wv.w, accP[m].w);
            }
        }
        #pragma unroll
        for (int m = 0; m < 4; ++m) {
            float4 tA, dF;
            tA.x = tanhf(accA[m].x); tA.y = tanhf(accA[m].y);
            tA.z = tanhf(accA[m].z); tA.w = tanhf(accA[m].w);
            dF.x = tanhf(accP[m].x) - tA.x; dF.y = tanhf(accP[m].y) - tA.y;
            dF.z = tanhf(accP[m].z) - tA.z; dF.w = tanhf(accP[m].w) - tA.w;
            *reinterpret_cast<float4*>(&s_avA [(g + 8 * m) * S1 + c0]) = tA;
            *reinterpret_cast<float4*>(&s_diff[(g + 8 * m) * S1 + c0]) = dF;
        }
    }
    __syncthreads();

    // =========================================================================
    // Phase 2a: score[i][j] = t[i,:] . states[j,:]  (scale folded into M).
    // Warp w produces rows 4w..4w+3 entirely locally.
    // =========================================================================
    {
        const int i0 = (tid >> 4) * 2;
        const int j0 = (tid & 15) * 2;
        float a00 = 0.f, a01 = 0.f, a10 = 0.f, a11 = 0.f;
        for (int kk = 0; kk < OBS; kk += 4) {
            float4 q0 = *reinterpret_cast<const float4*>(&s_t[ i0      * S1 + kk]);
            float4 q1 = *reinterpret_cast<const float4*>(&s_t[(i0 + 1) * S1 + kk]);
            float4 k0 = *reinterpret_cast<const float4*>(&s_states[ j0      * S1 + kk]);
            float4 k1 = *reinterpret_cast<const float4*>(&s_states[(j0 + 1) * S1 + kk]);
            a00 = fmaf(q0.x, k0.x, fmaf(q0.y, k0.y, fmaf(q0.z, k0.z, fmaf(q0.w, k0.w, a00))));
            a01 = fmaf(q0.x, k1.x, fmaf(q0.y, k1.y, fmaf(q0.z, k1.z, fmaf(q0.w, k1.w, a01))));
            a10 = fmaf(q1.x, k0.x, fmaf(q1.y, k0.y, fmaf(q1.z, k0.z, fmaf(q1.w, k0.w, a10))));
            a11 = fmaf(q1.x, k1.x, fmaf(q1.y, k1.y, fmaf(q1.z, k1.z, fmaf(q1.w, k1.w, a11))));
        }
        s_w[i0 * NA + j0]           = a00;
        s_w[i0 * NA + j0 + 1]       = a01;
        s_w[(i0 + 1) * NA + j0]     = a10;
        s_w[(i0 + 1) * NA + j0 + 1] = a11;
    }
    __syncwarp();

    // =========================================================================
    // Phase 2a': softmax — warp w owns rows 4w..4w+3 (warp-local sync only)
    // =========================================================================
    {
        const int warp = tid >> 5, lane = tid & 31;
        #pragma unroll
        for (int rr = 0; rr < 4; ++rr) {
            const int row = warp * 4 + rr;
            float v = s_w[row * NA + lane];
            float m = v;
            #pragma unroll
            for (int off = 16; off > 0; off >>= 1)
                m = fmaxf(m, __shfl_xor_sync(0xffffffffu, m, off));
            float e = expf(v - m);
            float s = e;
            #pragma unroll
            for (int off = 16; off > 0; off >>= 1)
                s += __shfl_xor_sync(0xffffffffu, s, off);
            float w = e / s;
            s_w[row * NA + lane] = w;
            weight_out[(size_t)b * NA * NA + row * NA + lane] = w;
        }
    }

    // =========================================================================
    // Phase 2b: aW1 = avA@W1, dW1 = diff@W1. 2 j-rows x 4 h per thread.
    // =========================================================================
    {
        const int j0 = (tid >> 4) * 2;
        const int h0 = (tid & 15) * 4;
        float4 aA0 = make_float4(0,0,0,0), aA1 = make_float4(0,0,0,0);
        float4 aD0 = make_float4(0,0,0,0), aD1 = make_float4(0,0,0,0);
        for (int d = 0; d < DV; d += 4) {
            float4 av0 = *reinterpret_cast<const float4*>(&s_avA [ j0      * S1 + d]);
            float4 av1 = *reinterpret_cast<const float4*>(&s_avA [(j0 + 1) * S1 + d]);
            float4 df0 = *reinterpret_cast<const float4*>(&s_diff[ j0      * S1 + d]);
            float4 df1 = *reinterpret_cast<const float4*>(&s_diff[(j0 + 1) * S1 + d]);
            #pragma unroll
            for (int t = 0; t < 4; ++t) {
                float4 w1 = *reinterpret_cast<const float4*>(&W1[(d + t) * DH + h0]);
                float a0 = reinterpret_cast<const float*>(&av0)[t];
                float a1 = reinterpret_cast<const float*>(&av1)[t];
                float d0 = reinterpret_cast<const float*>(&df0)[t];
                float d1 = reinterpret_cast<const float*>(&df1)[t];
                aA0.x = fmaf(a0, w1.x, aA0.x); aA0.y = fmaf(a0, w1.y, aA0.y);
                aA0.z = fmaf(a0, w1.z, aA0.z); aA0.w = fmaf(a0, w1.w, aA0.w);
                aA1.x = fmaf(a1, w1.x, aA1.x); aA1.y = fmaf(a1, w1.y, aA1.y);
                aA1.z = fmaf(a1, w1.z, aA1.z); aA1.w = fmaf(a1, w1.w, aA1.w);
                aD0.x = fmaf(d0, w1.x, aD0.x); aD0.y = fmaf(d0, w1.y, aD0.y);
                aD0.z = fmaf(d0, w1.z, aD0.z); aD0.w = fmaf(d0, w1.w, aD0.w);
                aD1.x = fmaf(d1, w1.x, aD1.x); aD1.y = fmaf(d1, w1.y, aD1.y);
                aD1.z = fmaf(d1, w1.z, aD1.z); aD1.w = fmaf(d1, w1.w, aD1.w);
            }
        }
        *reinterpret_cast<float4*>(&s_aW1[ j0      * S2 + h0]) = aA0;
        *reinterpret_cast<float4*>(&s_aW1[(j0 + 1) * S2 + h0]) = aA1;
        *reinterpret_cast<float4*>(&s_dW1[ j0      * S2 + h0]) = aD0;
        *reinterpret_cast<float4*>(&s_dW1[(j0 + 1) * S2 + h0]) = aD1;
    }
    __syncthreads();

    // =========================================================================
    // Phase 4: bW1 = w @ aW1   [32 x 64]
    // =========================================================================
    {
        const int a0 = (tid >> 4) * 2;
        const int h0 = (tid & 15) * 4;
        float4 acc0 = make_float4(0,0,0,0), acc1 = make_float4(0,0,0,0);
        for (int j = 0; j < NA; j += 4) {
            float4 w0 = *reinterpret_cast<const float4*>(&s_w[ a0      * NA + j]);
            float4 w1 = *reinterpret_cast<const float4*>(&s_w[(a0 + 1) * NA + j]);
            #pragma unroll
            for (int t = 0; t < 4; ++t) {
                float4 aw = *reinterpret_cast<const float4*>(&s_aW1[(j + t) * S2 + h0]);
                float v0 = reinterpret_cast<const float*>(&w0)[t];
                float v1 = reinterpret_cast<const float*>(&w1)[t];
                acc0.x = fmaf(v0, aw.x, acc0.x); acc0.y = fmaf(v0, aw.y, acc0.y);
                acc0.z = fmaf(v0, aw.z, acc0.z); acc0.w = fmaf(v0, aw.w, acc0.w);
                acc1.x = fmaf(v1, aw.x, acc1.x); acc1.y = fmaf(v1, aw.y, acc1.y);
                acc1.z = fmaf(v1, aw.z, acc1.z); acc1.w = fmaf(v1, aw.w, acc1.w);
            }
        }
        *reinterpret_cast<float4*>(&s_bW1[ a0      * S2 + h0]) = acc0;
        *reinterpret_cast<float4*>(&s_bW1[(a0 + 1) * S2 + h0]) = acc1;
    }
    __syncthreads();

    // =========================================================================
    // Phase 5: per (a,c): h = leaky(bW1[a] + w*dW1[c]); out = h @ W2.
    // 4 a-values per thread so dW1/W2 loads amortize.
    // =========================================================================
    {
        const int a0 = tid >> 5;      // 0..7
        const int c  = tid & 31;      // 0..31
        float wk[4];
        #pragma unroll
        for (int k = 0; k < 4; ++k) wk[k] = s_w[(a0 + 8 * k) * NA + c];

        float4 accL[4], accH[4];
        #pragma unroll
        for (int k = 0; k < 4; ++k) {
            accL[k] = make_float4(0,0,0,0);
            accH[k] = make_float4(0,0,0,0);
        }
        for (int h = 0; h < DH; h += 4) {
            float4 dq = *reinterpret_cast<const float4*>(&s_dW1[c * S2 + h]);
            float4 w2lo[4], w2hi[4];
            #pragma unroll
            for (int t = 0; t < 4; ++t) {
                w2lo[t] = *reinterpret_cast<const float4*>(&s_W2[(h + t) * DO]);
                w2hi[t] = *reinterpret_cast<const float4*>(&s_W2[(h + t) * DO + 4]);
            }
            #pragma unroll
            for (int k = 0; k < 4; ++k) {
                float4 bq = *reinterpret_cast<const float4*>(&s_bW1[(a0 + 8 * k) * S2 + h]);
                #pragma unroll
                for (int t = 0; t < 4; ++t) {
                    float x = fmaf(wk[k],
                                   reinterpret_cast<const float*>(&dq)[t],
                                   reinterpret_cast<const float*>(&bq)[t]);
                    x = fmaxf(x, 0.01f * x);   // leaky_relu(0.01)
                    accL[k].x = fmaf(x, w2lo[t].x, accL[k].x);
                    accL[k].y = fmaf(x, w2lo[t].y, accL[k].y);
                    accL[k].z = fmaf(x, w2lo[t].z, accL[k].z);
                    accL[k].w = fmaf(x, w2lo[t].w, accL[k].w);
                    accH[k].x = fmaf(x, w2hi[t].x, accH[k].x);
                    accH[k].y = fmaf(x, w2hi[t].y, accH[k].y);
                    accH[k].z = fmaf(x, w2hi[t].z, accH[k].z);
                    accH[k].w = fmaf(x, w2hi[t].w, accH[k].w);
                }
            }
        }
        #pragma unroll
        for (int k = 0; k < 4; ++k) {
            float4* outp = reinterpret_cast<float4*>(
                value_out + (((size_t)b * NA + (a0 + 8 * k)) * NA + c) * DO);
            outp[0] = accL[k];
            outp[1] = accH[k];
        }
    }
}

extern "C" void kernel_launch(void* const* d_in, const int* in_sizes, int n_in,
                              void* d_out, int out_size) {
    const float* states   = (const float*)d_in[0];
    const float* policies = (const float*)d_in[1];
    const float* actions  = (const float*)d_in[2];
    const float* Wk       = (const float*)d_in[3];
    const float* Wq       = (const float*)d_in[4];
    const float* Wv       = (const float*)d_in[5];
    const float* W1       = (const float*)d_in[6];
    const float* W2       = (const float*)d_in[7];

    float* value_out  = (float*)d_out;                              // [B,N,N,8]
    float* weight_out = value_out + (size_t)BATCH * NA * NA * DO;   // [B,N,N]

    compute_M_kernel<<<64, 256>>>(Wq, Wk);

    cudaFuncSetAttribute(critic_kernel,
                         cudaFuncAttributeMaxDynamicSharedMemorySize, SMEM_BYTES);
    critic_kernel<<<BATCH, 256, SMEM_BYTES>>>(
        states, policies, actions, Wv, W1, W2, value_out, weight_out);
}